// round 10
// baseline (speedup 1.0000x reference)
#include <cuda_runtime.h>
#include <cuda_fp16.h>
#include <cstdint>

#define VOCAB   8192
#define EMB     256
#define NROWS   16384
#define NCAND   12

// ---------------- global scratch ----------------
__device__ float g_e_half[VOCAB];
__device__ __align__(128) uint8_t g_z8[(size_t)NROWS * EMB];
__device__ __align__(128) uint8_t g_e8[(size_t)VOCAB * EMB];
__device__ int g_cand[NROWS * NCAND];
__device__ int g_amax_z = 0;   // float bits; atomicMax idempotent across replays
__device__ int g_amax_e = 0;

__device__ __forceinline__ uint32_t smem_u32(const void* p) {
    uint32_t a;
    asm("{ .reg .u64 t; cvta.to.shared.u64 t, %1; cvt.u32.u64 %0, t; }" : "=r"(a) : "l"(p));
    return a;
}
__device__ __forceinline__ void cp16(uint32_t dst, const void* src) {
    asm volatile("cp.async.cg.shared.global [%0], [%1], 16;" :: "r"(dst), "l"(src) : "memory");
}

// fp8 e4m3 MMA, f32 accumulate: m16n8k32
#define FMMA8(c, a, bv0, bv1) \
    asm volatile("mma.sync.aligned.m16n8k32.row.col.f32.e4m3.e4m3.f32 " \
        "{%0,%1,%2,%3}, {%4,%5,%6,%7}, {%8,%9}, {%0,%1,%2,%3};" \
        : "+f"((c)[0]), "+f"((c)[1]), "+f"((c)[2]), "+f"((c)[3]) \
        : "r"((a)[0]), "r"((a)[1]), "r"((a)[2]), "r"((a)[3]), "r"(bv0), "r"(bv1))

#define LDMX4(r, addr) \
    asm volatile("ldmatrix.sync.aligned.m8n8.x4.shared.b16 {%0,%1,%2,%3}, [%4];" \
        : "=r"((r)[0]), "=r"((r)[1]), "=r"((r)[2]), "=r"((r)[3]) : "r"(addr))

// pack two floats -> e4m3x2 (lo = a, hi = b)
__device__ __forceinline__ uint16_t cvt_e4m3x2(float lo, float hi) {
    uint16_t r;
    asm("cvt.rn.satfinite.e4m3x2.f32 %0, %1, %2;" : "=h"(r) : "f"(hi), "f"(lo));
    return r;
}

__device__ __forceinline__ float pow2_scale(float amax) {
    // largest power of 2 s with amax*s <= 448 (exact scaling, no rounding)
    if (!(amax > 0.f)) return 1.f;
    return exp2f(floorf(log2f(448.f / amax)));
}

// ---------------- prep kernels ----------------
__global__ void vq_amax_kernel(const float* __restrict__ z, const float* __restrict__ cb) {
    const int stride = gridDim.x * blockDim.x;
    int i = blockIdx.x * blockDim.x + threadIdx.x;
    float mz = 0.f, me = 0.f;
    for (int j = i; j < NROWS * EMB / 4; j += stride) {
        float4 v = ((const float4*)z)[j];
        mz = fmaxf(mz, fmaxf(fmaxf(fabsf(v.x), fabsf(v.y)), fmaxf(fabsf(v.z), fabsf(v.w))));
    }
    for (int j = i; j < VOCAB * EMB / 4; j += stride) {
        float4 v = ((const float4*)cb)[j];
        me = fmaxf(me, fmaxf(fmaxf(fabsf(v.x), fabsf(v.y)), fmaxf(fabsf(v.z), fabsf(v.w))));
    }
    #pragma unroll
    for (int o = 16; o > 0; o >>= 1) {
        mz = fmaxf(mz, __shfl_xor_sync(0xffffffffu, mz, o));
        me = fmaxf(me, __shfl_xor_sync(0xffffffffu, me, o));
    }
    if ((threadIdx.x & 31) == 0) {
        atomicMax(&g_amax_z, __float_as_int(mz));
        atomicMax(&g_amax_e, __float_as_int(me));
    }
}

__global__ void vq_quant_kernel(const float* __restrict__ z, const float* __restrict__ cb) {
    const float sz = pow2_scale(__int_as_float(g_amax_z));
    const float se = pow2_scale(__int_as_float(g_amax_e));
    const int NZ4 = NROWS * EMB / 4;
    const int NE4 = VOCAB * EMB / 4;
    int i = blockIdx.x * blockDim.x + threadIdx.x;
    if (i < NZ4) {
        float4 v = ((const float4*)z)[i];
        uint32_t lo = cvt_e4m3x2(v.x * sz, v.y * sz);
        uint32_t hi = cvt_e4m3x2(v.z * sz, v.w * sz);
        ((uint32_t*)g_z8)[i] = lo | (hi << 16);
    } else if (i < NZ4 + NE4) {
        int j = i - NZ4;
        float4 v = ((const float4*)cb)[j];
        uint32_t lo = cvt_e4m3x2(v.x * se, v.y * se);
        uint32_t hi = cvt_e4m3x2(v.z * se, v.w * se);
        ((uint32_t*)g_e8)[j] = lo | (hi << 16);
    }
}

__global__ void vq_prep_kernel(const float* __restrict__ cb, float* __restrict__ ref_out) {
    int gtid = blockIdx.x * blockDim.x + threadIdx.x;
    int warp = gtid >> 5;
    int lane = threadIdx.x & 31;
    if (warp < VOCAB) {
        const float4* row = (const float4*)(cb + (size_t)warp * EMB);
        float4 a = row[lane];
        float4 b = row[lane + 32];
        float s = a.x*a.x + a.y*a.y + a.z*a.z + a.w*a.w
                + b.x*b.x + b.y*b.y + b.z*b.z + b.w*b.w;
        #pragma unroll
        for (int o = 16; o > 0; o >>= 1) s += __shfl_xor_sync(0xffffffffu, s, o);
        if (lane == 0) g_e_half[warp] = 0.5f * s;
    }
    if (gtid < VOCAB) ref_out[gtid] = 0.0f;
}

// ---------------- phase 1: FP8 MMA GEMM + top-candidate select -------------
#define GCH     32                      // codes per chunk
#define NCHUNKS (VOCAB / GCH)           // 256
#define BBUF    8192                    // bytes per B stage (32 codes x 256B)
#define SM_EH   24576                   // after 3 B stages
#define SMEM_GB (SM_EH + VOCAB * 4)     // 57344

#define TOP3(s_, c_, v1, i1, v2, i2, v3, i3) { float _t = (s_); \
    if (_t > (v3)) { \
        if (_t > (v1))      { (v3)=(v2);(i3)=(i2); (v2)=(v1);(i2)=(i1); (v1)=_t;(i1)=(c_); } \
        else if (_t > (v2)) { (v3)=(v2);(i3)=(i2); (v2)=_t;(i2)=(c_); } \
        else                { (v3)=_t;(i3)=(c_); } } }

__global__ void __launch_bounds__(256, 1) vq_gemm_kernel() {
    extern __shared__ char sm[];
    const uint32_t sb = smem_u32(sm);
    const int tid  = threadIdx.x;
    const int lane = tid & 31;
    const int warp = tid >> 5;      // 0..7, each owns 16 rows
    const int blk  = blockIdx.x;

    const float sz = pow2_scale(__int_as_float(g_amax_z));
    const float se = pow2_scale(__int_as_float(g_amax_e));
    const float gscale = 1.f / (sz * se);

    // ---- stage this CTA's 128 z rows (256B each) swizzled into smem ----
    {
        const char* src = (const char*)g_z8 + (size_t)blk * 128 * 256;
        #pragma unroll
        for (int j = 0; j < 8; ++j) {
            int u = tid + j * 256;      // 0..2047 granules of 16B
            int n = u >> 4, g = u & 15;
            cp16(sb + n * 256 + ((g ^ (n & 7)) << 4), src + (size_t)u * 16);
        }
        asm volatile("cp.async.commit_group;" ::: "memory");
        asm volatile("cp.async.wait_group 0;" ::: "memory");
        __syncthreads();
    }

    // ---- resident A fragments: 8 k-blocks x 4 regs (16 rows/warp, k32 fp8) ----
    uint32_t A[8][4];
    {
        const int r = warp * 16 + (lane & 15);
        #pragma unroll
        for (int kb = 0; kb < 8; ++kb) {
            uint32_t addr = sb + r * 256 + (((2 * kb + (lane >> 4)) ^ (r & 7)) << 4);
            LDMX4(A[kb], addr);
        }
    }
    __syncthreads();   // smem reusable

    // ---- prologue: first two B chunks + e_half table ----
    {
        #pragma unroll
        for (int s = 0; s < 2; ++s) {
            const char* src = (const char*)g_e8 + (size_t)s * GCH * 256;
            uint32_t dstb = sb + s * BBUF;
            #pragma unroll
            for (int j = 0; j < 2; ++j) {
                int u = tid + j * 256;  // 0..511
                int n = u >> 4, g = u & 15;
                cp16(dstb + n * 256 + ((g ^ (n & 7)) << 4), src + (size_t)u * 16);
            }
            asm volatile("cp.async.commit_group;" ::: "memory");
        }
        for (int i = tid; i < VOCAB; i += 256)
            *(float*)(sm + SM_EH + i * 4) = g_e_half[i];
    }

    float acc[4][4];
    #pragma unroll
    for (int nb = 0; nb < 4; ++nb)
        #pragma unroll
        for (int q = 0; q < 4; ++q) acc[nb][q] = 0.f;

    // per-slot (2 rows) x top-3 per thread
    float tv1[2], tv2[2], tv3[2];
    int   ti1[2], ti2[2], ti3[2];
    #pragma unroll
    for (int s = 0; s < 2; ++s) {
        tv1[s] = tv2[s] = tv3[s] = -3.4e38f;
        ti1[s] = ti2[s] = ti3[s] = 0;
    }

    const int nbase = ((lane >> 4) & 1) * 8 + (lane & 7);
    const uint32_t brow0 = (uint32_t)nbase * 256;
    const uint32_t brow1 = (uint32_t)(nbase + 16) * 256;
    const int gb = (lane >> 3) & 1;
    const int sw = lane & 7;

    for (int ch = 0; ch < NCHUNKS; ++ch) {
        if (ch >= NCHUNKS - 1) asm volatile("cp.async.wait_group 0;" ::: "memory");
        else                   asm volatile("cp.async.wait_group 1;" ::: "memory");
        __syncthreads();

        const uint32_t bb = sb + (uint32_t)(ch % 3) * BBUF;

        // B register double-buffer
        uint32_t B0[2][4], B1[2][4];
        {
            const uint32_t go0 = (uint32_t)((gb ^ sw) << 4);
            LDMX4(B0[0], bb + brow0 + go0);
            LDMX4(B1[0], bb + brow1 + go0);
        }
        #pragma unroll
        for (int kb = 0; kb < 8; ++kb) {
            const int p = kb & 1;
            if (kb < 7) {
                const uint32_t go = (uint32_t)(((2 * (kb + 1) + gb) ^ sw) << 4);
                LDMX4(B0[p ^ 1], bb + brow0 + go);
                LDMX4(B1[p ^ 1], bb + brow1 + go);
            }
            FMMA8(acc[0], A[kb], B0[p][0], B0[p][1]);
            FMMA8(acc[1], A[kb], B0[p][2], B0[p][3]);
            FMMA8(acc[2], A[kb], B1[p][0], B1[p][1]);
            FMMA8(acc[3], A[kb], B1[p][2], B1[p][3]);
        }

        // epilogue: descale, fold -0.5||e||^2, per-slot top-3, reset acc
        const int c0 = ch * GCH + 2 * (lane & 3);
        #pragma unroll
        for (int nb = 0; nb < 4; ++nb) {
            const int ca = c0 + nb * 8;
            const float2 eh = *(const float2*)(sm + SM_EH + (size_t)ca * 4);
            TOP3(acc[nb][0] * gscale - eh.x, ca,     tv1[0], ti1[0], tv2[0], ti2[0], tv3[0], ti3[0]);
            TOP3(acc[nb][1] * gscale - eh.y, ca + 1, tv1[0], ti1[0], tv2[0], ti2[0], tv3[0], ti3[0]);
            TOP3(acc[nb][2] * gscale - eh.x, ca,     tv1[1], ti1[1], tv2[1], ti2[1], tv3[1], ti3[1]);
            TOP3(acc[nb][3] * gscale - eh.y, ca + 1, tv1[1], ti1[1], tv2[1], ti2[1], tv3[1], ti3[1]);
            acc[nb][0] = 0.f; acc[nb][1] = 0.f; acc[nb][2] = 0.f; acc[nb][3] = 0.f;
        }

        // prefetch chunk ch+2
        if (ch + 2 < NCHUNKS) {
            const char* src = (const char*)g_e8 + (size_t)(ch + 2) * GCH * 256;
            uint32_t dstb = sb + (uint32_t)((ch + 2) % 3) * BBUF;
            #pragma unroll
            for (int j = 0; j < 2; ++j) {
                int u = tid + j * 256;
                int n = u >> 4, g = u & 15;
                cp16(dstb + n * 256 + ((g ^ (n & 7)) << 4), src + (size_t)u * 16);
            }
            asm volatile("cp.async.commit_group;" ::: "memory");
        }
    }

    // ---- write candidates: quad threads own disjoint code subsets ----
    // row for slot s = blk*128 + warp*16 + s*8 + (lane>>2); d = lane&3
    const int d = lane & 3;
    #pragma unroll
    for (int s = 0; s < 2; ++s) {
        const int row = blk * 128 + warp * 16 + s * 8 + (lane >> 2);
        g_cand[row * NCAND + d * 3 + 0] = ti1[s];
        g_cand[row * NCAND + d * 3 + 1] = ti2[s];
        g_cand[row * NCAND + d * 3 + 2] = ti3[s];
    }
}

// ---------------- phase 2: exact fp32 rescore (12 cands) + outputs ---------
__global__ void __launch_bounds__(256) vq_rescore_kernel(
    const float* __restrict__ z, const float* __restrict__ cb,
    float* __restrict__ tok, float* __restrict__ zq, float* __restrict__ ref) {
    const int warp = threadIdx.x >> 5, lane = threadIdx.x & 31;
    const int row  = blockIdx.x * 8 + warp;

    int cand[NCAND];
    #pragma unroll
    for (int k = 0; k < NCAND; ++k) cand[k] = g_cand[row * NCAND + k];

    const float4* zr = (const float4*)(z + (size_t)row * EMB);
    const float4 z0 = zr[lane * 2], z1 = zr[lane * 2 + 1];

    float best = -3.4e38f;
    int   bi   = 0x7fffffff;

    #pragma unroll
    for (int g = 0; g < NCAND / 4; ++g) {
        // load 4 candidate rows (MLP), then 4 parallel reductions
        float dot[4];
        #pragma unroll
        for (int j = 0; j < 4; ++j) {
            const int c = cand[g * 4 + j];
            const float4* er = (const float4*)(cb + (size_t)c * EMB);
            const float4 e0 = er[lane * 2], e1 = er[lane * 2 + 1];
            dot[j] = z0.x*e0.x + z0.y*e0.y + z0.z*e0.z + z0.w*e0.w
                   + z1.x*e1.x + z1.y*e1.y + z1.z*e1.z + z1.w*e1.w;
        }
        #pragma unroll
        for (int o = 16; o > 0; o >>= 1) {
            #pragma unroll
            for (int j = 0; j < 4; ++j)
                dot[j] += __shfl_xor_sync(0xffffffffu, dot[j], o);
        }
        #pragma unroll
        for (int j = 0; j < 4; ++j) {
            const int   c = cand[g * 4 + j];
            const float s = dot[j] - g_e_half[c];
            if (s > best || (s == best && c < bi)) { best = s; bi = c; }
        }
    }

    tok[row] = (float)bi;
    if (lane == 0) atomicAdd(&ref[bi], 1.0f);
    const float4* eb = (const float4*)(cb + (size_t)bi * EMB);
    float4* o = (float4*)(zq + (size_t)row * EMB);
    o[lane * 2]     = eb[lane * 2];
    o[lane * 2 + 1] = eb[lane * 2 + 1];
}

// ---------------- launch ----------------------------------------------------
extern "C" void kernel_launch(void* const* d_in, const int* in_sizes, int n_in,
                              void* d_out, int out_size) {
    const float* z;
    const float* cb;
    if (in_sizes[0] == NROWS * EMB) { z = (const float*)d_in[0]; cb = (const float*)d_in[1]; }
    else                            { z = (const float*)d_in[1]; cb = (const float*)d_in[0]; }

    float* out = (float*)d_out;
    float* tok = out;
    float* zq  = out + NROWS;
    float* ref = out + NROWS + (size_t)NROWS * EMB;

    cudaFuncSetAttribute(vq_gemm_kernel, cudaFuncAttributeMaxDynamicSharedMemorySize, SMEM_GB);

    vq_amax_kernel<<<592, 256>>>(z, cb);
    const int nconv = (NROWS * EMB / 4) + (VOCAB * EMB / 4);
    vq_quant_kernel<<<(nconv + 255) / 256, 256>>>(z, cb);
    vq_prep_kernel<<<(VOCAB * 32) / 256, 256>>>(cb, ref);
    vq_gemm_kernel<<<NROWS / 128, 256, SMEM_GB>>>();
    vq_rescore_kernel<<<NROWS / 8, 256>>>(z, cb, tok, zq, ref);
}

// round 11
// speedup vs baseline: 1.5140x; 1.5140x over previous
#include <cuda_runtime.h>
#include <cuda_bf16.h>
#include <cstdint>

#define VOCAB   8192
#define EMB     256
#define NROWS   16384
#define NCAND   16
#define NUNITS  1024        // 128 m-tiles x 8 v-chunks
#define VCH     1024        // codes per v-chunk
#define GCH     32          // codes per B chunk
#define CPU_    32          // chunks per unit (VCH/GCH)

// ---------------- global scratch ----------------
__device__ float g_e_half[VOCAB];
__device__ __align__(128) __nv_bfloat16 g_zb[(size_t)NROWS * EMB];
__device__ __align__(128) __nv_bfloat16 g_eb[(size_t)VOCAB * EMB];
__device__ int g_cand[NROWS * NCAND];

__device__ __forceinline__ uint32_t smem_u32(const void* p) {
    uint32_t a;
    asm("{ .reg .u64 t; cvta.to.shared.u64 t, %1; cvt.u32.u64 %0, t; }" : "=r"(a) : "l"(p));
    return a;
}
__device__ __forceinline__ void cp16(uint32_t dst, const void* src) {
    asm volatile("cp.async.cg.shared.global [%0], [%1], 16;" :: "r"(dst), "l"(src) : "memory");
}

#define MMA16816(c, a, bv0, bv1) \
    asm volatile("mma.sync.aligned.m16n8k16.row.col.f32.bf16.bf16.f32 " \
        "{%0,%1,%2,%3}, {%4,%5,%6,%7}, {%8,%9}, {%0,%1,%2,%3};" \
        : "+f"((c)[0]), "+f"((c)[1]), "+f"((c)[2]), "+f"((c)[3]) \
        : "r"((a)[0]), "r"((a)[1]), "r"((a)[2]), "r"((a)[3]), "r"(bv0), "r"(bv1))

#define LDMX4(r, addr) \
    asm volatile("ldmatrix.sync.aligned.m8n8.x4.shared.b16 {%0,%1,%2,%3}, [%4];" \
        : "=r"((r)[0]), "=r"((r)[1]), "=r"((r)[2]), "=r"((r)[3]) : "r"(addr))

// ---------------- prep kernels ----------------
__device__ __forceinline__ uint32_t pack_bf2(float a, float b) {
    __nv_bfloat162 h = __floats2bfloat162_rn(a, b);
    return *(uint32_t*)&h;
}

__global__ void vq_convert_kernel(const float* __restrict__ z, const float* __restrict__ cb) {
    const int NZ4 = NROWS * EMB / 4;
    const int NE4 = VOCAB * EMB / 4;
    int i = blockIdx.x * blockDim.x + threadIdx.x;
    if (i < NZ4) {
        float4 v = ((const float4*)z)[i];
        ((uint2*)g_zb)[i] = make_uint2(pack_bf2(v.x, v.y), pack_bf2(v.z, v.w));
    } else if (i < NZ4 + NE4) {
        int j = i - NZ4;
        float4 v = ((const float4*)cb)[j];
        ((uint2*)g_eb)[j] = make_uint2(pack_bf2(v.x, v.y), pack_bf2(v.z, v.w));
    }
}

__global__ void vq_prep_kernel(const float* __restrict__ cb, float* __restrict__ ref_out) {
    int gtid = blockIdx.x * blockDim.x + threadIdx.x;
    int warp = gtid >> 5;
    int lane = threadIdx.x & 31;
    if (warp < VOCAB) {
        const float4* row = (const float4*)(cb + (size_t)warp * EMB);
        float4 a = row[lane];
        float4 b = row[lane + 32];
        float s = a.x*a.x + a.y*a.y + a.z*a.z + a.w*a.w
                + b.x*b.x + b.y*b.y + b.z*b.z + b.w*b.w;
        #pragma unroll
        for (int o = 16; o > 0; o >>= 1) s += __shfl_xor_sync(0xffffffffu, s, o);
        if (lane == 0) g_e_half[warp] = 0.5f * s;
    }
    if (gtid < VOCAB) ref_out[gtid] = 0.0f;
}

// ---------------- phase 1: persistent HMMA GEMM + per-unit top-2 -----------
#define BBUF    16384                   // bytes per B stage (32 codes x 512B)
#define SM_B    0                       // 3 x 16384 = 49152
#define SM_EH   49152                   // 32768
#define SM_A    81920                   // 128 rows x 512B = 65536
#define SMEM_GB 147456

#define TOP2(s_, c_, v1, i1, v2, i2) { float _t = (s_); \
    if (_t > (v2)) { if (_t > (v1)) { (v2)=(v1); (i2)=(i1); (v1)=_t; (i1)=(c_); } \
                     else          { (v2)=_t;  (i2)=(c_); } } }

#define INS4(s_, c_) { float _u = (s_); int _d = (c_); \
    if (_u > w3) { \
        if (_u > w1) { \
            if (_u > w0) { w3=w2;q3=q2; w2=w1;q2=q1; w1=w0;q1=q0; w0=_u;q0=_d; } \
            else         { w3=w2;q3=q2; w2=w1;q2=q1; w1=_u;q1=_d; } \
        } else { \
            if (_u > w2) { w3=w2;q3=q2; w2=_u;q2=_d; } \
            else         { w3=_u;q3=_d; } \
        } } }

__global__ void __launch_bounds__(128, 1) vq_gemm_kernel() {
    extern __shared__ char sm[];
    const uint32_t sb = smem_u32(sm);
    const int tid  = threadIdx.x;
    const int lane = tid & 31;
    const int warp = tid >> 5;

    // contiguous unit range for this CTA
    const int u0 = (NUNITS * blockIdx.x) / gridDim.x;
    const int u1 = (NUNITS * (blockIdx.x + 1)) / gridDim.x;
    const int T  = (u1 - u0) * CPU_;    // flat chunk count

    // e_half table (once)
    for (int i = tid; i < VOCAB; i += 128)
        *(float*)(sm + SM_EH + i * 4) = g_e_half[i];
    __syncthreads();

    // prime B prefetch for flat chunks 0,1
    #pragma unroll
    for (int p = 0; p < 2; ++p) {
        const int up = u0 + (p >> 5);
        const size_t code0 = (size_t)((up & 7) * VCH + (p & 31) * GCH);
        const char* src = (const char*)g_eb + code0 * 512;
        uint32_t dstb = sb + SM_B + (uint32_t)(p % 3) * BBUF;
        #pragma unroll
        for (int j = 0; j < 8; ++j) {
            int uu = tid + j * 128;
            int n = uu >> 5, g = uu & 31;
            cp16(dstb + n * 512 + ((g ^ (n & 7)) << 4), src + (size_t)uu * 16);
        }
        asm volatile("cp.async.commit_group;" ::: "memory");
    }

    uint32_t A[2][16][4];
    float acc[2][4][4];
    #pragma unroll
    for (int mb = 0; mb < 2; ++mb)
        #pragma unroll
        for (int nb = 0; nb < 4; ++nb)
            #pragma unroll
            for (int q = 0; q < 4; ++q) acc[mb][nb][q] = 0.f;

    float tv1[4], tv2[4];
    int   ti1[4], ti2[4];

    const int nbase = ((lane >> 4) & 1) * 8 + (lane & 7);
    const uint32_t brow0 = (uint32_t)nbase * 512;
    const uint32_t brow1 = (uint32_t)(nbase + 16) * 512;
    const int gb = (lane >> 3) & 1;
    const int sw = lane & 7;

    int cur_m = -1;

    for (int t = 0; t < T; ++t) {
        const int u = u0 + (t >> 5);
        const int m = u >> 3;
        const int v = u & 7;
        const int c = t & 31;

        if (c == 0) {
            if (m != cur_m) {
                // ---- (re)load A tile for m-tile m ----
                asm volatile("cp.async.wait_group 0;" ::: "memory");
                __syncthreads();
                const char* srcA = (const char*)g_zb + (size_t)m * 128 * 512;
                #pragma unroll
                for (int j = 0; j < 32; ++j) {
                    int uu = tid + j * 128;
                    int n = uu >> 5, g = uu & 31;
                    cp16(sb + SM_A + n * 512 + ((g ^ (n & 7)) << 4), srcA + (size_t)uu * 16);
                }
                asm volatile("cp.async.commit_group;" ::: "memory");
                asm volatile("cp.async.wait_group 0;" ::: "memory");
                __syncthreads();
                #pragma unroll
                for (int mb = 0; mb < 2; ++mb) {
                    const int r = warp * 32 + mb * 16 + (lane & 8) + (lane & 7);
                    #pragma unroll
                    for (int kb = 0; kb < 16; ++kb) {
                        uint32_t addr = sb + SM_A + r * 512 + (((2 * kb + (lane >> 4)) ^ (lane & 7)) << 4);
                        LDMX4(A[mb][kb], addr);
                    }
                }
                cur_m = m;
            }
            // reset per-unit top-2
            #pragma unroll
            for (int s = 0; s < 4; ++s) { tv1[s] = -3.4e38f; tv2[s] = -3.4e38f; ti1[s] = 0; ti2[s] = 0; }
        }

        if (t >= T - 1) asm volatile("cp.async.wait_group 0;" ::: "memory");
        else            asm volatile("cp.async.wait_group 1;" ::: "memory");
        __syncthreads();

        const uint32_t bb = sb + SM_B + (uint32_t)(t % 3) * BBUF;

        #pragma unroll
        for (int kb = 0; kb < 16; ++kb) {
            uint32_t b0r[4], b1r[4];
            const uint32_t go = (uint32_t)(((2 * kb + gb) ^ sw) << 4);
            LDMX4(b0r, bb + brow0 + go);   // n-blocks 0,1
            LDMX4(b1r, bb + brow1 + go);   // n-blocks 2,3
            #pragma unroll
            for (int mb = 0; mb < 2; ++mb) {
                MMA16816(acc[mb][0], A[mb][kb], b0r[0], b0r[1]);
                MMA16816(acc[mb][1], A[mb][kb], b0r[2], b0r[3]);
                MMA16816(acc[mb][2], A[mb][kb], b1r[0], b1r[1]);
                MMA16816(acc[mb][3], A[mb][kb], b1r[2], b1r[3]);
            }
        }

        // epilogue: fold -0.5||e||^2, per-row top-2, reset acc
        const int c0 = v * VCH + c * GCH + 2 * (lane & 3);
        #pragma unroll
        for (int nb = 0; nb < 4; ++nb) {
            const int ca = c0 + nb * 8;
            const float2 eh = *(const float2*)(sm + SM_EH + (size_t)ca * 4);
            #pragma unroll
            for (int mb = 0; mb < 2; ++mb) {
                const int s0 = mb * 2, s1 = mb * 2 + 1;
                TOP2(acc[mb][nb][0] - eh.x, ca,     tv1[s0], ti1[s0], tv2[s0], ti2[s0]);
                TOP2(acc[mb][nb][1] - eh.y, ca + 1, tv1[s0], ti1[s0], tv2[s0], ti2[s0]);
                TOP2(acc[mb][nb][2] - eh.x, ca,     tv1[s1], ti1[s1], tv2[s1], ti2[s1]);
                TOP2(acc[mb][nb][3] - eh.y, ca + 1, tv1[s1], ti1[s1], tv2[s1], ti2[s1]);
                acc[mb][nb][0] = 0.f; acc[mb][nb][1] = 0.f;
                acc[mb][nb][2] = 0.f; acc[mb][nb][3] = 0.f;
            }
        }

        // prefetch flat chunk t+2
        if (t + 2 < T) {
            const int p  = t + 2;
            const int up = u0 + (p >> 5);
            const size_t code0 = (size_t)((up & 7) * VCH + (p & 31) * GCH);
            const char* src = (const char*)g_eb + code0 * 512;
            uint32_t dstb = sb + SM_B + (uint32_t)(p % 3) * BBUF;
            #pragma unroll
            for (int j = 0; j < 8; ++j) {
                int uu = tid + j * 128;
                int n = uu >> 5, g = uu & 31;
                cp16(dstb + n * 512 + ((g ^ (n & 7)) << 4), src + (size_t)uu * 16);
            }
            asm volatile("cp.async.commit_group;" ::: "memory");
        }

        if (c == 31) {
            // ---- unit done: quad-merge to per-row top-2, write g_cand ----
            #pragma unroll
            for (int slot = 0; slot < 4; ++slot) {
                float w0 = tv1[slot], w1 = tv2[slot], w2 = -3.4e38f, w3 = -3.4e38f;
                int   q0 = ti1[slot], q1 = ti2[slot], q2 = 0, q3 = 0;
                #pragma unroll
                for (int d = 1; d <= 2; d <<= 1) {
                    float o0 = __shfl_xor_sync(0xffffffffu, w0, d);
                    float o1 = __shfl_xor_sync(0xffffffffu, w1, d);
                    float o2 = __shfl_xor_sync(0xffffffffu, w2, d);
                    float o3 = __shfl_xor_sync(0xffffffffu, w3, d);
                    int   p0 = __shfl_xor_sync(0xffffffffu, q0, d);
                    int   p1 = __shfl_xor_sync(0xffffffffu, q1, d);
                    int   p2 = __shfl_xor_sync(0xffffffffu, q2, d);
                    int   p3 = __shfl_xor_sync(0xffffffffu, q3, d);
                    INS4(o0, p0); INS4(o1, p1); INS4(o2, p2); INS4(o3, p3);
                }
                if ((lane & 3) == 0) {
                    const int row = m * 128 + warp * 32 + slot * 8 + (lane >> 2);
                    g_cand[row * NCAND + v * 2 + 0] = q0;
                    g_cand[row * NCAND + v * 2 + 1] = q1;
                }
            }
        }
    }
}

// ---------------- phase 2: exact fp32 rescore (16 cands) + outputs ---------
__global__ void __launch_bounds__(256) vq_rescore_kernel(
    const float* __restrict__ z, const float* __restrict__ cb,
    float* __restrict__ tok, float* __restrict__ zq, float* __restrict__ ref) {
    const int warp = threadIdx.x >> 5, lane = threadIdx.x & 31;
    const int row  = blockIdx.x * 8 + warp;

    int cand[NCAND];
    #pragma unroll
    for (int k = 0; k < NCAND; ++k) cand[k] = g_cand[row * NCAND + k];

    const float4* zr = (const float4*)(z + (size_t)row * EMB);
    const float4 z0 = zr[lane * 2], z1 = zr[lane * 2 + 1];

    float best = -3.4e38f;
    int   bi   = 0x7fffffff;

    #pragma unroll
    for (int g = 0; g < NCAND / 4; ++g) {
        float dot[4];
        #pragma unroll
        for (int j = 0; j < 4; ++j) {
            const int c = cand[g * 4 + j];
            const float4* er = (const float4*)(cb + (size_t)c * EMB);
            const float4 e0 = er[lane * 2], e1 = er[lane * 2 + 1];
            dot[j] = z0.x*e0.x + z0.y*e0.y + z0.z*e0.z + z0.w*e0.w
                   + z1.x*e1.x + z1.y*e1.y + z1.z*e1.z + z1.w*e1.w;
        }
        #pragma unroll
        for (int o = 16; o > 0; o >>= 1) {
            #pragma unroll
            for (int j = 0; j < 4; ++j)
                dot[j] += __shfl_xor_sync(0xffffffffu, dot[j], o);
        }
        #pragma unroll
        for (int j = 0; j < 4; ++j) {
            const int   c = cand[g * 4 + j];
            const float s = dot[j] - g_e_half[c];
            if (s > best || (s == best && c < bi)) { best = s; bi = c; }
        }
    }

    tok[row] = (float)bi;
    if (lane == 0) atomicAdd(&ref[bi], 1.0f);
    const float4* eb = (const float4*)(cb + (size_t)bi * EMB);
    float4* o = (float4*)(zq + (size_t)row * EMB);
    o[lane * 2]     = eb[lane * 2];
    o[lane * 2 + 1] = eb[lane * 2 + 1];
}

// ---------------- launch ----------------------------------------------------
extern "C" void kernel_launch(void* const* d_in, const int* in_sizes, int n_in,
                              void* d_out, int out_size) {
    const float* z;
    const float* cb;
    if (in_sizes[0] == NROWS * EMB) { z = (const float*)d_in[0]; cb = (const float*)d_in[1]; }
    else                            { z = (const float*)d_in[1]; cb = (const float*)d_in[0]; }

    float* out = (float*)d_out;
    float* tok = out;
    float* zq  = out + NROWS;
    float* ref = out + NROWS + (size_t)NROWS * EMB;

    int dev = 0, nsm = 0;
    cudaGetDevice(&dev);
    if (cudaDeviceGetAttribute(&nsm, cudaDevAttrMultiProcessorCount, dev) != cudaSuccess || nsm <= 0)
        nsm = 148;
    if (nsm > NUNITS) nsm = NUNITS;

    cudaFuncSetAttribute(vq_gemm_kernel, cudaFuncAttributeMaxDynamicSharedMemorySize, SMEM_GB);

    const int nconv = (NROWS * EMB / 4) + (VOCAB * EMB / 4);
    vq_convert_kernel<<<(nconv + 255) / 256, 256>>>(z, cb);
    vq_prep_kernel<<<(VOCAB * 32) / 256, 256>>>(cb, ref);
    vq_gemm_kernel<<<nsm, 128, SMEM_GB>>>();
    vq_rescore_kernel<<<NROWS / 8, 256>>>(z, cb, tok, zq, ref);
}

// round 12
// speedup vs baseline: 1.6935x; 1.1185x over previous
#include <cuda_runtime.h>
#include <cuda_bf16.h>
#include <cstdint>

#define VOCAB   8192
#define EMB     256
#define NROWS   16384
#define NCAND   16
#define NUNITS  1024        // 128 m-tiles x 8 v-chunks
#define VCH     1024        // codes per v-chunk
#define GCH     32          // codes per B chunk
#define CPU_    32          // chunks per unit (VCH/GCH)

// ---------------- global scratch ----------------
__device__ float g_e_half[VOCAB];
__device__ __align__(128) __nv_bfloat16 g_zb[(size_t)NROWS * EMB];
__device__ __align__(128) __nv_bfloat16 g_eb[(size_t)VOCAB * EMB];
__device__ int   g_cand[NROWS * NCAND];
__device__ float g_cval[NROWS * NCAND];

__device__ __forceinline__ uint32_t smem_u32(const void* p) {
    uint32_t a;
    asm("{ .reg .u64 t; cvta.to.shared.u64 t, %1; cvt.u32.u64 %0, t; }" : "=r"(a) : "l"(p));
    return a;
}
__device__ __forceinline__ void cp16(uint32_t dst, const void* src) {
    asm volatile("cp.async.cg.shared.global [%0], [%1], 16;" :: "r"(dst), "l"(src) : "memory");
}

#define MMA16816(c, a, bv0, bv1) \
    asm volatile("mma.sync.aligned.m16n8k16.row.col.f32.bf16.bf16.f32 " \
        "{%0,%1,%2,%3}, {%4,%5,%6,%7}, {%8,%9}, {%0,%1,%2,%3};" \
        : "+f"((c)[0]), "+f"((c)[1]), "+f"((c)[2]), "+f"((c)[3]) \
        : "r"((a)[0]), "r"((a)[1]), "r"((a)[2]), "r"((a)[3]), "r"(bv0), "r"(bv1))

#define LDMX4(r, addr) \
    asm volatile("ldmatrix.sync.aligned.m8n8.x4.shared.b16 {%0,%1,%2,%3}, [%4];" \
        : "=r"((r)[0]), "=r"((r)[1]), "=r"((r)[2]), "=r"((r)[3]) : "r"(addr))

// ---------------- prep kernels ----------------
__device__ __forceinline__ uint32_t pack_bf2(float a, float b) {
    __nv_bfloat162 h = __floats2bfloat162_rn(a, b);
    return *(uint32_t*)&h;
}

__global__ void vq_convert_kernel(const float* __restrict__ z, const float* __restrict__ cb) {
    const int NZ4 = NROWS * EMB / 4;
    const int NE4 = VOCAB * EMB / 4;
    int i = blockIdx.x * blockDim.x + threadIdx.x;
    if (i < NZ4) {
        float4 v = ((const float4*)z)[i];
        ((uint2*)g_zb)[i] = make_uint2(pack_bf2(v.x, v.y), pack_bf2(v.z, v.w));
    } else if (i < NZ4 + NE4) {
        int j = i - NZ4;
        float4 v = ((const float4*)cb)[j];
        ((uint2*)g_eb)[j] = make_uint2(pack_bf2(v.x, v.y), pack_bf2(v.z, v.w));
    }
}

__global__ void vq_prep_kernel(const float* __restrict__ cb, float* __restrict__ ref_out) {
    int gtid = blockIdx.x * blockDim.x + threadIdx.x;
    int warp = gtid >> 5;
    int lane = threadIdx.x & 31;
    if (warp < VOCAB) {
        const float4* row = (const float4*)(cb + (size_t)warp * EMB);
        float4 a = row[lane];
        float4 b = row[lane + 32];
        float s = a.x*a.x + a.y*a.y + a.z*a.z + a.w*a.w
                + b.x*b.x + b.y*b.y + b.z*b.z + b.w*b.w;
        #pragma unroll
        for (int o = 16; o > 0; o >>= 1) s += __shfl_xor_sync(0xffffffffu, s, o);
        if (lane == 0) g_e_half[warp] = 0.5f * s;
    }
    if (gtid < VOCAB) ref_out[gtid] = 0.0f;
}

// ---------------- phase 1: persistent HMMA GEMM + per-unit top-2 -----------
#define BBUF    16384                   // bytes per B stage (32 codes x 512B)
#define SM_B    0                       // 4 x 16384 = 65536
#define SM_EH   65536                   // 32768
#define SM_A    98304                   // 128 rows x 512B = 65536
#define SMEM_GB 163840

#define TOP2(s_, c_, v1, i1, v2, i2) { float _t = (s_); \
    if (_t > (v2)) { if (_t > (v1)) { (v2)=(v1); (i2)=(i1); (v1)=_t; (i1)=(c_); } \
                     else          { (v2)=_t;  (i2)=(c_); } } }

#define INS4(s_, c_) { float _u = (s_); int _d = (c_); \
    if (_u > w3) { \
        if (_u > w1) { \
            if (_u > w0) { w3=w2;q3=q2; w2=w1;q2=q1; w1=w0;q1=q0; w0=_u;q0=_d; } \
            else         { w3=w2;q3=q2; w2=w1;q2=q1; w1=_u;q1=_d; } \
        } else { \
            if (_u > w2) { w3=w2;q3=q2; w2=_u;q2=_d; } \
            else         { w3=_u;q3=_d; } \
        } } }

__global__ void __launch_bounds__(128, 1) vq_gemm_kernel() {
    extern __shared__ char sm[];
    const uint32_t sb = smem_u32(sm);
    const int tid  = threadIdx.x;
    const int lane = tid & 31;
    const int warp = tid >> 5;

    // contiguous unit range for this CTA
    const int u0 = (NUNITS * blockIdx.x) / gridDim.x;
    const int u1 = (NUNITS * (blockIdx.x + 1)) / gridDim.x;
    const int T  = (u1 - u0) * CPU_;    // flat chunk count (multiple of 32)

    // e_half table (once)
    for (int i = tid; i < VOCAB; i += 128)
        *(float*)(sm + SM_EH + i * 4) = g_e_half[i];
    __syncthreads();

    // prime B prefetch for flat chunks 0,1
    #pragma unroll
    for (int p = 0; p < 2; ++p) {
        const int up = u0 + (p >> 5);
        const size_t code0 = (size_t)((up & 7) * VCH + (p & 31) * GCH);
        const char* src = (const char*)g_eb + code0 * 512;
        uint32_t dstb = sb + SM_B + (uint32_t)(p & 3) * BBUF;
        #pragma unroll
        for (int j = 0; j < 8; ++j) {
            int uu = tid + j * 128;
            int n = uu >> 5, g = uu & 31;
            cp16(dstb + n * 512 + ((g ^ (n & 7)) << 4), src + (size_t)uu * 16);
        }
        asm volatile("cp.async.commit_group;" ::: "memory");
    }

    uint32_t A[2][16][4];
    float acc[2][4][4];
    #pragma unroll
    for (int mb = 0; mb < 2; ++mb)
        #pragma unroll
        for (int nb = 0; nb < 4; ++nb)
            #pragma unroll
            for (int q = 0; q < 4; ++q) acc[mb][nb][q] = 0.f;

    float tv1[4], tv2[4];
    int   ti1[4], ti2[4];

    const int nbase = ((lane >> 4) & 1) * 8 + (lane & 7);
    const uint32_t brow0 = (uint32_t)nbase * 512;
    const uint32_t brow1 = (uint32_t)(nbase + 16) * 512;
    const int gb = (lane >> 3) & 1;
    const int sw = lane & 7;

    int cur_m = -1;

    for (int tt = 0; tt < T; tt += 2) {
        const int u = u0 + (tt >> 5);
        const int m = u >> 3;
        const int v = u & 7;

        if ((tt & 31) == 0) {
            if (m != cur_m) {
                // ---- (re)load A tile for m-tile m ----
                asm volatile("cp.async.wait_group 0;" ::: "memory");
                __syncthreads();
                const char* srcA = (const char*)g_zb + (size_t)m * 128 * 512;
                #pragma unroll
                for (int j = 0; j < 32; ++j) {
                    int uu = tid + j * 128;
                    int n = uu >> 5, g = uu & 31;
                    cp16(sb + SM_A + n * 512 + ((g ^ (n & 7)) << 4), srcA + (size_t)uu * 16);
                }
                asm volatile("cp.async.commit_group;" ::: "memory");
                asm volatile("cp.async.wait_group 0;" ::: "memory");
                __syncthreads();
                #pragma unroll
                for (int mb = 0; mb < 2; ++mb) {
                    const int r = warp * 32 + mb * 16 + (lane & 8) + (lane & 7);
                    #pragma unroll
                    for (int kb = 0; kb < 16; ++kb) {
                        uint32_t addr = sb + SM_A + r * 512 + (((2 * kb + (lane >> 4)) ^ (lane & 7)) << 4);
                        LDMX4(A[mb][kb], addr);
                    }
                }
                cur_m = m;
            }
            // reset per-unit top-2
            #pragma unroll
            for (int s = 0; s < 4; ++s) { tv1[s] = -3.4e38f; tv2[s] = -3.4e38f; ti1[s] = 0; ti2[s] = 0; }
        }

        // wait for chunks tt, tt+1 (nothing else outstanding -> no false stall)
        asm volatile("cp.async.wait_group 0;" ::: "memory");
        __syncthreads();

        // prefetch chunks tt+2, tt+3 into the two free buffers
        #pragma unroll
        for (int q = 0; q < 2; ++q) {
            const int p = tt + 2 + q;
            if (p < T) {
                const int up = u0 + (p >> 5);
                const size_t code0 = (size_t)((up & 7) * VCH + (p & 31) * GCH);
                const char* src = (const char*)g_eb + code0 * 512;
                uint32_t dstb = sb + SM_B + (uint32_t)(p & 3) * BBUF;
                #pragma unroll
                for (int j = 0; j < 8; ++j) {
                    int uu = tid + j * 128;
                    int n = uu >> 5, g = uu & 31;
                    cp16(dstb + n * 512 + ((g ^ (n & 7)) << 4), src + (size_t)uu * 16);
                }
                asm volatile("cp.async.commit_group;" ::: "memory");
            }
        }

        // process the two ready chunks
        #pragma unroll
        for (int h = 0; h < 2; ++h) {
            const int t  = tt + h;
            const int cc = t & 31;
            const uint32_t bb = sb + SM_B + (uint32_t)(t & 3) * BBUF;

            #pragma unroll
            for (int kb = 0; kb < 16; ++kb) {
                uint32_t b0r[4], b1r[4];
                const uint32_t go = (uint32_t)(((2 * kb + gb) ^ sw) << 4);
                LDMX4(b0r, bb + brow0 + go);   // n-blocks 0,1
                LDMX4(b1r, bb + brow1 + go);   // n-blocks 2,3
                #pragma unroll
                for (int mb = 0; mb < 2; ++mb) {
                    MMA16816(acc[mb][0], A[mb][kb], b0r[0], b0r[1]);
                    MMA16816(acc[mb][1], A[mb][kb], b0r[2], b0r[3]);
                    MMA16816(acc[mb][2], A[mb][kb], b1r[0], b1r[1]);
                    MMA16816(acc[mb][3], A[mb][kb], b1r[2], b1r[3]);
                }
            }

            // epilogue: fold -0.5||e||^2, per-row top-2, reset acc
            const int c0 = v * VCH + cc * GCH + 2 * (lane & 3);
            #pragma unroll
            for (int nb = 0; nb < 4; ++nb) {
                const int ca = c0 + nb * 8;
                const float2 eh = *(const float2*)(sm + SM_EH + (size_t)ca * 4);
                #pragma unroll
                for (int mb = 0; mb < 2; ++mb) {
                    const int s0 = mb * 2, s1 = mb * 2 + 1;
                    TOP2(acc[mb][nb][0] - eh.x, ca,     tv1[s0], ti1[s0], tv2[s0], ti2[s0]);
                    TOP2(acc[mb][nb][1] - eh.y, ca + 1, tv1[s0], ti1[s0], tv2[s0], ti2[s0]);
                    TOP2(acc[mb][nb][2] - eh.x, ca,     tv1[s1], ti1[s1], tv2[s1], ti2[s1]);
                    TOP2(acc[mb][nb][3] - eh.y, ca + 1, tv1[s1], ti1[s1], tv2[s1], ti2[s1]);
                    acc[mb][nb][0] = 0.f; acc[mb][nb][1] = 0.f;
                    acc[mb][nb][2] = 0.f; acc[mb][nb][3] = 0.f;
                }
            }
        }

        if ((tt & 31) == 30) {
            // ---- unit done: quad-merge to per-row top-2, write g_cand/g_cval ----
            #pragma unroll
            for (int slot = 0; slot < 4; ++slot) {
                float w0 = tv1[slot], w1 = tv2[slot], w2 = -3.4e38f, w3 = -3.4e38f;
                int   q0 = ti1[slot], q1 = ti2[slot], q2 = 0, q3 = 0;
                #pragma unroll
                for (int d = 1; d <= 2; d <<= 1) {
                    float o0 = __shfl_xor_sync(0xffffffffu, w0, d);
                    float o1 = __shfl_xor_sync(0xffffffffu, w1, d);
                    float o2 = __shfl_xor_sync(0xffffffffu, w2, d);
                    float o3 = __shfl_xor_sync(0xffffffffu, w3, d);
                    int   p0 = __shfl_xor_sync(0xffffffffu, q0, d);
                    int   p1 = __shfl_xor_sync(0xffffffffu, q1, d);
                    int   p2 = __shfl_xor_sync(0xffffffffu, q2, d);
                    int   p3 = __shfl_xor_sync(0xffffffffu, q3, d);
                    INS4(o0, p0); INS4(o1, p1); INS4(o2, p2); INS4(o3, p3);
                }
                if ((lane & 3) == 0) {
                    const int row = m * 128 + warp * 32 + slot * 8 + (lane >> 2);
                    g_cand[row * NCAND + v * 2 + 0] = q0;
                    g_cand[row * NCAND + v * 2 + 1] = q1;
                    g_cval[row * NCAND + v * 2 + 0] = w0;
                    g_cval[row * NCAND + v * 2 + 1] = w1;
                }
            }
        }
    }
}

// ---------------- phase 2: margin-gated exact rescore + outputs ------------
#define MARGIN_THRESH 0.5f

__global__ void __launch_bounds__(256) vq_rescore_kernel(
    const float* __restrict__ z, const float* __restrict__ cb,
    float* __restrict__ tok, float* __restrict__ zq, float* __restrict__ ref) {
    const int warp = threadIdx.x >> 5, lane = threadIdx.x & 31;
    const int row  = blockIdx.x * 8 + warp;

    // approx (val, idx) per lane (lanes 0..15 hold candidates)
    float av = -3.4e38f;
    int   ac = 0x7fffffff;
    if (lane < NCAND) {
        av = g_cval[row * NCAND + lane];
        ac = g_cand[row * NCAND + lane];
    }
    // warp top-1 (lowest index on value tie)
    float bv = av; int bidx = ac;
    #pragma unroll
    for (int o = 16; o > 0; o >>= 1) {
        float ov = __shfl_xor_sync(0xffffffffu, bv, o);
        int   oi = __shfl_xor_sync(0xffffffffu, bidx, o);
        if (ov > bv || (ov == bv && oi < bidx)) { bv = ov; bidx = oi; }
    }
    // second-best value (exclude winner's lane; candidate indices are distinct)
    float v2 = (ac == bidx) ? -3.4e38f : av;
    #pragma unroll
    for (int o = 16; o > 0; o >>= 1)
        v2 = fmaxf(v2, __shfl_xor_sync(0xffffffffu, v2, o));

    int bi;
    if (bv - v2 > MARGIN_THRESH) {
        bi = bidx;   // approx winner certain (bf16 dot error bound << margin)
    } else {
        // full exact fp32 rescore over all 16 candidates
        int cand[NCAND];
        #pragma unroll
        for (int k = 0; k < NCAND; ++k) cand[k] = g_cand[row * NCAND + k];

        const float4* zr = (const float4*)(z + (size_t)row * EMB);
        const float4 z0 = zr[lane * 2], z1 = zr[lane * 2 + 1];

        float best = -3.4e38f;
        bi = 0x7fffffff;
        #pragma unroll
        for (int g = 0; g < NCAND / 4; ++g) {
            float dot[4];
            #pragma unroll
            for (int j = 0; j < 4; ++j) {
                const int c = cand[g * 4 + j];
                const float4* er = (const float4*)(cb + (size_t)c * EMB);
                const float4 e0 = er[lane * 2], e1 = er[lane * 2 + 1];
                dot[j] = z0.x*e0.x + z0.y*e0.y + z0.z*e0.z + z0.w*e0.w
                       + z1.x*e1.x + z1.y*e1.y + z1.z*e1.z + z1.w*e1.w;
            }
            #pragma unroll
            for (int o = 16; o > 0; o >>= 1) {
                #pragma unroll
                for (int j = 0; j < 4; ++j)
                    dot[j] += __shfl_xor_sync(0xffffffffu, dot[j], o);
            }
            #pragma unroll
            for (int j = 0; j < 4; ++j) {
                const int   c = cand[g * 4 + j];
                const float s = dot[j] - g_e_half[c];
                if (s > best || (s == best && c < bi)) { best = s; bi = c; }
            }
        }
    }

    tok[row] = (float)bi;
    if (lane == 0) atomicAdd(&ref[bi], 1.0f);
    const float4* eb = (const float4*)(cb + (size_t)bi * EMB);
    float4* o = (float4*)(zq + (size_t)row * EMB);
    o[lane * 2]     = eb[lane * 2];
    o[lane * 2 + 1] = eb[lane * 2 + 1];
}

// ---------------- launch ----------------------------------------------------
extern "C" void kernel_launch(void* const* d_in, const int* in_sizes, int n_in,
                              void* d_out, int out_size) {
    const float* z;
    const float* cb;
    if (in_sizes[0] == NROWS * EMB) { z = (const float*)d_in[0]; cb = (const float*)d_in[1]; }
    else                            { z = (const float*)d_in[1]; cb = (const float*)d_in[0]; }

    float* out = (float*)d_out;
    float* tok = out;
    float* zq  = out + NROWS;
    float* ref = out + NROWS + (size_t)NROWS * EMB;

    int dev = 0, nsm = 0;
    cudaGetDevice(&dev);
    if (cudaDeviceGetAttribute(&nsm, cudaDevAttrMultiProcessorCount, dev) != cudaSuccess || nsm <= 0)
        nsm = 148;
    if (nsm > NUNITS) nsm = NUNITS;

    cudaFuncSetAttribute(vq_gemm_kernel, cudaFuncAttributeMaxDynamicSharedMemorySize, SMEM_GB);

    const int nconv = (NROWS * EMB / 4) + (VOCAB * EMB / 4);
    vq_convert_kernel<<<(nconv + 255) / 256, 256>>>(z, cb);
    vq_prep_kernel<<<(VOCAB * 32) / 256, 256>>>(cb, ref);
    vq_gemm_kernel<<<nsm, 128, SMEM_GB>>>();
    vq_rescore_kernel<<<NROWS / 8, 256>>>(z, cb, tok, zq, ref);
}

// round 14
// speedup vs baseline: 1.7593x; 1.0388x over previous
#include <cuda_runtime.h>
#include <cuda_bf16.h>
#include <cstdint>

#define VOCAB   8192
#define EMB     256
#define NROWS   16384
#define NCAND   16
#define NUNITS  1024        // 128 m-tiles x 8 v-chunks
#define VCH     1024        // codes per v-chunk
#define GCH     32          // codes per B chunk
#define CPU_    32          // chunks per unit (VCH/GCH)

// ---------------- global scratch ----------------
__device__ float g_e_half[VOCAB];
__device__ __align__(128) __nv_bfloat16 g_eb[(size_t)VOCAB * EMB];
__device__ int   g_cand[NROWS * NCAND];
__device__ float g_cval[NROWS * NCAND];

__device__ __forceinline__ uint32_t smem_u32(const void* p) {
    uint32_t a;
    asm("{ .reg .u64 t; cvta.to.shared.u64 t, %1; cvt.u32.u64 %0, t; }" : "=r"(a) : "l"(p));
    return a;
}
__device__ __forceinline__ void cp16(uint32_t dst, const void* src) {
    asm volatile("cp.async.cg.shared.global [%0], [%1], 16;" :: "r"(dst), "l"(src) : "memory");
}

#define MMA16816(c, a, bv0, bv1) \
    asm volatile("mma.sync.aligned.m16n8k16.row.col.f32.bf16.bf16.f32 " \
        "{%0,%1,%2,%3}, {%4,%5,%6,%7}, {%8,%9}, {%0,%1,%2,%3};" \
        : "+f"((c)[0]), "+f"((c)[1]), "+f"((c)[2]), "+f"((c)[3]) \
        : "r"((a)[0]), "r"((a)[1]), "r"((a)[2]), "r"((a)[3]), "r"(bv0), "r"(bv1))

#define LDMX4(r, addr) \
    asm volatile("ldmatrix.sync.aligned.m8n8.x4.shared.b16 {%0,%1,%2,%3}, [%4];" \
        : "=r"((r)[0]), "=r"((r)[1]), "=r"((r)[2]), "=r"((r)[3]) : "r"(addr))

__device__ __forceinline__ uint32_t pack_bf2(float a, float b) {
    __nv_bfloat162 h = __floats2bfloat162_rn(a, b);
    return *(uint32_t*)&h;
}

// ---------------- prep: cb->bf16 convert + e_half + ref zero ----------------
__global__ void vq_prep_kernel(const float* __restrict__ cb, float* __restrict__ ref_out) {
    const int gtid = blockIdx.x * blockDim.x + threadIdx.x;
    const int NE4 = VOCAB * EMB / 4;               // 524288; grid covers this
    if (gtid < NE4) {
        float4 v = ((const float4*)cb)[gtid];
        ((uint2*)g_eb)[gtid] = make_uint2(pack_bf2(v.x, v.y), pack_bf2(v.z, v.w));
    }
    const int warp = gtid >> 5;
    const int lane = threadIdx.x & 31;
    if (warp < VOCAB) {
        const float4* row = (const float4*)(cb + (size_t)warp * EMB);
        float4 a = row[lane];
        float4 b = row[lane + 32];
        float s = a.x*a.x + a.y*a.y + a.z*a.z + a.w*a.w
                + b.x*b.x + b.y*b.y + b.z*b.z + b.w*b.w;
        #pragma unroll
        for (int o = 16; o > 0; o >>= 1) s += __shfl_xor_sync(0xffffffffu, s, o);
        if (lane == 0) g_e_half[warp] = 0.5f * s;
    }
    if (gtid < VOCAB) ref_out[gtid] = 0.0f;
}

// ---------------- phase 1: persistent HMMA GEMM + per-unit top-2 -----------
#define BBUF    16384                   // bytes per B stage (32 codes x 512B)
#define SM_B    0                       // 4 x 16384 = 65536
#define SM_EH   65536                   // 32768
#define SM_A    98304                   // 128 rows x 512B = 65536
#define SMEM_GB 163840

#define TOP2(s_, c_, v1, i1, v2, i2) { float _t = (s_); \
    if (_t > (v2)) { if (_t > (v1)) { (v2)=(v1); (i2)=(i1); (v1)=_t; (i1)=(c_); } \
                     else          { (v2)=_t;  (i2)=(c_); } } }

#define INS4(s_, c_) { float _u = (s_); int _d = (c_); \
    if (_u > w3) { \
        if (_u > w1) { \
            if (_u > w0) { w3=w2;q3=q2; w2=w1;q2=q1; w1=w0;q1=q0; w0=_u;q0=_d; } \
            else         { w3=w2;q3=q2; w2=w1;q2=q1; w1=_u;q1=_d; } \
        } else { \
            if (_u > w2) { w3=w2;q3=q2; w2=_u;q2=_d; } \
            else         { w3=_u;q3=_d; } \
        } } }

__global__ void __launch_bounds__(128, 1) vq_gemm_kernel(const float* __restrict__ z) {
    extern __shared__ char sm[];
    const uint32_t sb = smem_u32(sm);
    const int tid  = threadIdx.x;
    const int lane = tid & 31;
    const int warp = tid >> 5;

    // contiguous unit range for this CTA
    const int u0 = (NUNITS * blockIdx.x) / gridDim.x;
    const int u1 = (NUNITS * (blockIdx.x + 1)) / gridDim.x;
    const int T  = (u1 - u0) * CPU_;    // flat chunk count (multiple of 32)

    // e_half table (once)
    for (int i = tid; i < VOCAB; i += 128)
        *(float*)(sm + SM_EH + i * 4) = g_e_half[i];
    __syncthreads();

    // prime B prefetch for flat chunks 0,1
    #pragma unroll
    for (int p = 0; p < 2; ++p) {
        const int up = u0 + (p >> 5);
        const size_t code0 = (size_t)((up & 7) * VCH + (p & 31) * GCH);
        const char* src = (const char*)g_eb + code0 * 512;
        uint32_t dstb = sb + SM_B + (uint32_t)(p & 3) * BBUF;
        #pragma unroll
        for (int j = 0; j < 8; ++j) {
            int uu = tid + j * 128;
            int n = uu >> 5, g = uu & 31;
            cp16(dstb + n * 512 + ((g ^ (n & 7)) << 4), src + (size_t)uu * 16);
        }
        asm volatile("cp.async.commit_group;" ::: "memory");
    }

    uint32_t A[2][16][4];
    float acc[2][4][4];
    #pragma unroll
    for (int mb = 0; mb < 2; ++mb)
        #pragma unroll
        for (int nb = 0; nb < 4; ++nb)
            #pragma unroll
            for (int q = 0; q < 4; ++q) acc[mb][nb][q] = 0.f;

    float tv1[4], tv2[4];
    int   ti1[4], ti2[4];

    const int nbase = ((lane >> 4) & 1) * 8 + (lane & 7);
    const uint32_t brow0 = (uint32_t)nbase * 512;
    const uint32_t brow1 = (uint32_t)(nbase + 16) * 512;
    const int gb = (lane >> 3) & 1;
    const int sw = lane & 7;

    int cur_m = -1;

    for (int tt = 0; tt < T; tt += 2) {
        const int u = u0 + (tt >> 5);
        const int m = u >> 3;
        const int v = u & 7;

        if ((tt & 31) == 0) {
            if (m != cur_m) {
                // ---- (re)load A tile: LDG fp32 -> bf16 STS (swizzled) ----
                __syncthreads();   // prior readers of SM_A done; converge
                const float* srcA = z + (size_t)m * 128 * 256;
                #pragma unroll
                for (int j = 0; j < 32; ++j) {        // 4096 granules: full 128 rows
                    int uu = tid + j * 128;           // granule 0..4095
                    int n = uu >> 5, g = uu & 31;
                    const float4 f0 = *(const float4*)(srcA + n * 256 + g * 8);
                    const float4 f1 = *(const float4*)(srcA + n * 256 + g * 8 + 4);
                    uint4 val;
                    val.x = pack_bf2(f0.x, f0.y);
                    val.y = pack_bf2(f0.z, f0.w);
                    val.z = pack_bf2(f1.x, f1.y);
                    val.w = pack_bf2(f1.z, f1.w);
                    *(uint4*)(sm + SM_A + n * 512 + ((g ^ (n & 7)) << 4)) = val;
                }
                __syncthreads();
                #pragma unroll
                for (int mb = 0; mb < 2; ++mb) {
                    const int r = warp * 32 + mb * 16 + (lane & 8) + (lane & 7);
                    #pragma unroll
                    for (int kb = 0; kb < 16; ++kb) {
                        uint32_t addr = sb + SM_A + r * 512 + (((2 * kb + (lane >> 4)) ^ (lane & 7)) << 4);
                        LDMX4(A[mb][kb], addr);
                    }
                }
                cur_m = m;
            }
            // reset per-unit top-2
            #pragma unroll
            for (int s = 0; s < 4; ++s) { tv1[s] = -3.4e38f; tv2[s] = -3.4e38f; ti1[s] = 0; ti2[s] = 0; }
        }

        // wait for chunks tt, tt+1
        asm volatile("cp.async.wait_group 0;" ::: "memory");
        __syncthreads();

        // prefetch chunks tt+2, tt+3 into the two free buffers
        #pragma unroll
        for (int q = 0; q < 2; ++q) {
            const int p = tt + 2 + q;
            if (p < T) {
                const int up = u0 + (p >> 5);
                const size_t code0 = (size_t)((up & 7) * VCH + (p & 31) * GCH);
                const char* src = (const char*)g_eb + code0 * 512;
                uint32_t dstb = sb + SM_B + (uint32_t)(p & 3) * BBUF;
                #pragma unroll
                for (int j = 0; j < 8; ++j) {
                    int uu = tid + j * 128;
                    int n = uu >> 5, g = uu & 31;
                    cp16(dstb + n * 512 + ((g ^ (n & 7)) << 4), src + (size_t)uu * 16);
                }
                asm volatile("cp.async.commit_group;" ::: "memory");
            }
        }

        // process the two ready chunks
        #pragma unroll
        for (int h = 0; h < 2; ++h) {
            const int t  = tt + h;
            const int cc = t & 31;
            const uint32_t bb = sb + SM_B + (uint32_t)(t & 3) * BBUF;

            #pragma unroll
            for (int kb = 0; kb < 16; ++kb) {
                uint32_t b0r[4], b1r[4];
                const uint32_t go = (uint32_t)(((2 * kb + gb) ^ sw) << 4);
                LDMX4(b0r, bb + brow0 + go);   // n-blocks 0,1
                LDMX4(b1r, bb + brow1 + go);   // n-blocks 2,3
                #pragma unroll
                for (int mb = 0; mb < 2; ++mb) {
                    MMA16816(acc[mb][0], A[mb][kb], b0r[0], b0r[1]);
                    MMA16816(acc[mb][1], A[mb][kb], b0r[2], b0r[3]);
                    MMA16816(acc[mb][2], A[mb][kb], b1r[0], b1r[1]);
                    MMA16816(acc[mb][3], A[mb][kb], b1r[2], b1r[3]);
                }
            }

            // epilogue: fold -0.5||e||^2, per-row top-2, reset acc
            const int c0 = v * VCH + cc * GCH + 2 * (lane & 3);
            #pragma unroll
            for (int nb = 0; nb < 4; ++nb) {
                const int ca = c0 + nb * 8;
                const float2 eh = *(const float2*)(sm + SM_EH + (size_t)ca * 4);
                #pragma unroll
                for (int mb = 0; mb < 2; ++mb) {
                    const int s0 = mb * 2, s1 = mb * 2 + 1;
                    TOP2(acc[mb][nb][0] - eh.x, ca,     tv1[s0], ti1[s0], tv2[s0], ti2[s0]);
                    TOP2(acc[mb][nb][1] - eh.y, ca + 1, tv1[s0], ti1[s0], tv2[s0], ti2[s0]);
                    TOP2(acc[mb][nb][2] - eh.x, ca,     tv1[s1], ti1[s1], tv2[s1], ti2[s1]);
                    TOP2(acc[mb][nb][3] - eh.y, ca + 1, tv1[s1], ti1[s1], tv2[s1], ti2[s1]);
                    acc[mb][nb][0] = 0.f; acc[mb][nb][1] = 0.f;
                    acc[mb][nb][2] = 0.f; acc[mb][nb][3] = 0.f;
                }
            }
        }

        if ((tt & 31) == 30) {
            // ---- unit done: quad-merge to per-row top-2, write g_cand/g_cval ----
            #pragma unroll
            for (int slot = 0; slot < 4; ++slot) {
                float w0 = tv1[slot], w1 = tv2[slot], w2 = -3.4e38f, w3 = -3.4e38f;
                int   q0 = ti1[slot], q1 = ti2[slot], q2 = 0, q3 = 0;
                #pragma unroll
                for (int d = 1; d <= 2; d <<= 1) {
                    float o0 = __shfl_xor_sync(0xffffffffu, w0, d);
                    float o1 = __shfl_xor_sync(0xffffffffu, w1, d);
                    float o2 = __shfl_xor_sync(0xffffffffu, w2, d);
                    float o3 = __shfl_xor_sync(0xffffffffu, w3, d);
                    int   p0 = __shfl_xor_sync(0xffffffffu, q0, d);
                    int   p1 = __shfl_xor_sync(0xffffffffu, q1, d);
                    int   p2 = __shfl_xor_sync(0xffffffffu, q2, d);
                    int   p3 = __shfl_xor_sync(0xffffffffu, q3, d);
                    INS4(o0, p0); INS4(o1, p1); INS4(o2, p2); INS4(o3, p3);
                }
                if ((lane & 3) == 0) {
                    const int row = m * 128 + warp * 32 + slot * 8 + (lane >> 2);
                    g_cand[row * NCAND + v * 2 + 0] = q0;
                    g_cand[row * NCAND + v * 2 + 1] = q1;
                    g_cval[row * NCAND + v * 2 + 0] = w0;
                    g_cval[row * NCAND + v * 2 + 1] = w1;
                }
            }
        }
    }
}

// ---------------- phase 2: eligible-subset exact rescore + outputs ---------
#define ERRB 0.4f   // two-sided bf16-score error bound (7.7 sigma one-sided)

__global__ void __launch_bounds__(256) vq_rescore_kernel(
    const float* __restrict__ z, const float* __restrict__ cb,
    float* __restrict__ tok, float* __restrict__ zq, float* __restrict__ ref) {
    const int warp = threadIdx.x >> 5, lane = threadIdx.x & 31;
    const int row  = blockIdx.x * 8 + warp;

    // approx (val, idx) per lane (lanes 0..15 hold candidates; indices distinct)
    float av = -3.4e38f;
    int   ac = 0x7fffffff;
    if (lane < NCAND) {
        av = g_cval[row * NCAND + lane];
        ac = g_cand[row * NCAND + lane];
    }
    // warp top-1 (lowest index on value tie)
    float bv = av; int bidx = ac;
    #pragma unroll
    for (int o = 16; o > 0; o >>= 1) {
        float ov = __shfl_xor_sync(0xffffffffu, bv, o);
        int   oi = __shfl_xor_sync(0xffffffffu, bidx, o);
        if (ov > bv || (ov == bv && oi < bidx)) { bv = ov; bidx = oi; }
    }

    // eligible set: only candidates within ERRB of the approx best can win
    const unsigned elig = __ballot_sync(0xffffffffu, lane < NCAND && av >= bv - ERRB);

    int bi;
    if (__popc(elig) == 1) {
        bi = bidx;                       // certain: exact order cannot flip
    } else {
        const float4* zr = (const float4*)(z + (size_t)row * EMB);
        const float4 z0 = zr[lane * 2], z1 = zr[lane * 2 + 1];
        float best = -3.4e38f;
        bi = 0x7fffffff;
        unsigned msk = elig;
        while (msk) {
            const int l = __ffs(msk) - 1; msk &= msk - 1;
            const int c = __shfl_sync(0xffffffffu, ac, l);
            const float4* er = (const float4*)(cb + (size_t)c * EMB);
            const float4 e0 = er[lane * 2], e1 = er[lane * 2 + 1];
            float d = z0.x*e0.x + z0.y*e0.y + z0.z*e0.z + z0.w*e0.w
                    + z1.x*e1.x + z1.y*e1.y + z1.z*e1.z + z1.w*e1.w;
            #pragma unroll
            for (int o = 16; o > 0; o >>= 1) d += __shfl_xor_sync(0xffffffffu, d, o);
            const float s = d - g_e_half[c];
            if (s > best || (s == best && c < bi)) { best = s; bi = c; }
        }
    }

    tok[row] = (float)bi;
    if (lane == 0) atomicAdd(&ref[bi], 1.0f);
    const float4* eb = (const float4*)(cb + (size_t)bi * EMB);
    float4* o = (float4*)(zq + (size_t)row * EMB);
    o[lane * 2]     = eb[lane * 2];
    o[lane * 2 + 1] = eb[lane * 2 + 1];
}

// ---------------- launch ----------------------------------------------------
extern "C" void kernel_launch(void* const* d_in, const int* in_sizes, int n_in,
                              void* d_out, int out_size) {
    const float* z;
    const float* cb;
    if (in_sizes[0] == NROWS * EMB) { z = (const float*)d_in[0]; cb = (const float*)d_in[1]; }
    else                            { z = (const float*)d_in[1]; cb = (const float*)d_in[0]; }

    float* out = (float*)d_out;
    float* tok = out;
    float* zq  = out + NROWS;
    float* ref = out + NROWS + (size_t)NROWS * EMB;

    int dev = 0, nsm = 0;
    cudaGetDevice(&dev);
    if (cudaDeviceGetAttribute(&nsm, cudaDevAttrMultiProcessorCount, dev) != cudaSuccess || nsm <= 0)
        nsm = 148;
    if (nsm > NUNITS) nsm = NUNITS;

    cudaFuncSetAttribute(vq_gemm_kernel, cudaFuncAttributeMaxDynamicSharedMemorySize, SMEM_GB);

    vq_prep_kernel<<<(VOCAB * EMB / 4) / 256, 256>>>(cb, ref);
    vq_gemm_kernel<<<nsm, 128, SMEM_GB>>>(z);
    vq_rescore_kernel<<<NROWS / 8, 256>>>(z, cb, tok, zq, ref);
}